// round 4
// baseline (speedup 1.0000x reference)
#include <cuda_runtime.h>

// Pyramid Givens circuit, n = m = 512, B = 256.
// Layer t in [0,1021): gates (i,i+1) for i ≡ t (mod 2), 0 <= i <= min(t, 1020-t).
// theta index: q=(t+i)/2, tidx = q(q+1)/2 + q - i.  Gate: a'=c*a+s*b ; b'=c*b-s*a.
//
// Decomposition: each row handled by 2 warps (halves h=0,1). Lane L of half h
// owns wires w..w+7, w = 256h + 8L, packed P[k] = (v_k, v_{k+4}), k=0..3.
// Even layer: rotp(P0,P1) [gates (w,w+1),(w+4,w+5)], rotp(P2,P3) [(w+2,w+3),(w+6,w+7)].
// Odd layer:  rotp(P1,P2) [(w+1,w+2),(w+5,w+6)], rotp(P3,Q) [(w+3,w+4),(w+7,w+8)],
//             Q=(P0.hi, v_{w+8}); new v0 computed redundantly from left gate (w-1,w).
// Half 1 is only touched for t in [254,765] (triangle) -> skipped outside.

#define N_WIRES   512
#define CHUNK_L   6                    // layers per cp.async chunk (3 stages)
#define NCHUNK    172                  // 516 stages, layers 0..1031 (tail identity)
#define T_PAD     (NCHUNK * CHUNK_L)   // 1032
#define LAYER_B   2560                 // 128 rot entries * 16B + 64 left * 8B
#define LEFT_OFF  2048
#define CHUNK_B   (CHUNK_L * LAYER_B)  // 15360

typedef unsigned long long ull;

// Per layer t (stride LAYER_B):
//   [0,2048): rot double2 {c2,s2}, entry ((h*2+r)*32 + lane)*16
//   [2048,2560): left-gate float2 (c,s), entry (h*32+lane)*8  (gate (w-1, w))
// Inactive gates stored as identity (1,0).
__device__ __align__(16) char g_tab[(size_t)T_PAD * LAYER_B];   // ~2.6 MB

__device__ __forceinline__ float2 cs_of(const float* __restrict__ th, int t, int i) {
    if (t <= 1020 && i >= 0 && i <= t && i <= 1020 - t && (((i ^ t) & 1) == 0)) {
        int q = (t + i) >> 1;
        int tidx = (q * (q + 1)) / 2 + q - i;
        float s, c;
        sincosf(th[tidx], &s, &c);
        return make_float2(c, s);
    }
    return make_float2(1.0f, 0.0f);
}

__global__ void build_cs_kernel(const float* __restrict__ thetas) {
    int t    = blockIdx.x;            // 0..T_PAD-1 (t > 1020 -> identity)
    int h    = threadIdx.x >> 6;      // 0,1
    int r    = (threadIdx.x >> 5) & 1;
    int lane = threadIdx.x & 31;
    int w    = 256 * h + 8 * lane;
    int ilo, ihi;
    if ((t & 1) == 0) { ilo = w + 2 * r;     ihi = ilo + 4; }
    else              { ilo = w + 2 * r + 1; ihi = ilo + 4; }
    float2 a = cs_of(thetas, t, ilo);
    float2 b = cs_of(thetas, t, ihi);
    char* base = g_tab + (size_t)t * LAYER_B;
    float2* dst = reinterpret_cast<float2*>(base + ((h * 2 + r) * 32 + lane) * 16);
    dst[0] = make_float2(a.x, b.x);   // c2
    dst[1] = make_float2(a.y, b.y);   // s2
    if (r == 0) {
        float2 lf = cs_of(thetas, t, w - 1);   // identity for w==0 or parity mismatch
        *reinterpret_cast<float2*>(base + LEFT_OFF + (h * 32 + lane) * 8) = lf;
    }
}

// ---- f32x2 helpers ----
__device__ __forceinline__ ull mul2(ull a, ull b) {
    ull d; asm("mul.rn.f32x2 %0, %1, %2;" : "=l"(d) : "l"(a), "l"(b)); return d;
}
__device__ __forceinline__ ull fma2(ull a, ull b, ull c) {
    ull d; asm("fma.rn.f32x2 %0, %1, %2, %3;" : "=l"(d) : "l"(a), "l"(b), "l"(c)); return d;
}
__device__ __forceinline__ float lo_f(ull p) {
    float lo, hi; asm("mov.b64 {%0, %1}, %2;" : "=f"(lo), "=f"(hi) : "l"(p)); return lo;
}
__device__ __forceinline__ float hi_f(ull p) {
    float lo, hi; asm("mov.b64 {%0, %1}, %2;" : "=f"(lo), "=f"(hi) : "l"(p)); return hi;
}
__device__ __forceinline__ ull pk(float lo, float hi) {
    ull d; asm("mov.b64 %0, {%1, %2};" : "=l"(d) : "f"(lo), "f"(hi)); return d;
}

#define SGNMASK 0x8000000080000000ULL

__device__ __forceinline__ void rotp(ull& a, ull& b, double2 cs) {
    ull c2 = __double_as_longlong(cs.x);
    ull s2 = __double_as_longlong(cs.y);
    ull t1 = mul2(s2, b);
    ull na = fma2(c2, a, t1);
    ull t2 = mul2(s2, a) ^ SGNMASK;
    b = fma2(c2, b, t2);
    a = na;
}

__device__ __forceinline__ void cp16(char* dst_smem, const char* src) {
    unsigned d = (unsigned)__cvta_generic_to_shared(dst_smem);
    asm volatile("cp.async.cg.shared.global [%0], [%1], 16;" :: "r"(d), "l"(src));
}
__device__ __forceinline__ void cp_commit() { asm volatile("cp.async.commit_group;"); }
__device__ __forceinline__ void cp_wait1()  { asm volatile("cp.async.wait_group 1;" ::: "memory"); }
__device__ __forceinline__ void bar_pair(int id) {
    asm volatile("bar.sync %0, 64;" :: "r"(id) : "memory");
}

// block = 128 threads: warps (0,1) = row 2b, warps (2,3) = row 2b+1.
__global__ void __launch_bounds__(128, 1) apply_kernel(
    const float* __restrict__ x,
    const float* __restrict__ bias,
    float* __restrict__ out)
{
    __shared__ __align__(16) char sbuf[3][CHUNK_B];   // 46080 B
    __shared__ float seam[2][2][2];                   // [rowInCta][stage parity][0:v255, 1:v256]

    const int tid  = threadIdx.x;
    const int wid  = tid >> 5;
    const int lane = tid & 31;
    const int rp   = wid >> 1;               // row in CTA: 0,1
    const int h    = wid & 1;                // half-row
    const int row  = blockIdx.x * 2 + rp;
    const int w    = 256 * h;                // + 8*lane implicit in layout

    if (tid < 8) ((float*)seam)[tid] = 0.0f;

    // Load 8 wires: x[row*512 + w + 8*lane + {0..7}], pack P[k]=(v_k, v_{k+4})
    ull P[4];
    {
        const float4* xr = reinterpret_cast<const float4*>(x + (size_t)row * N_WIRES + w) + lane * 2;
        float4 f0 = xr[0], f1 = xr[1];
        P[0] = pk(f0.x, f1.x);
        P[1] = pk(f0.y, f1.y);
        P[2] = pk(f0.z, f1.z);
        P[3] = pk(f0.w, f1.w);
    }

    // prologue: chunks 0,1 -> buffers 0,1
    #pragma unroll 1
    for (int pc = 0; pc < 2; ++pc) {
        const char* src = g_tab + (size_t)pc * CHUNK_B;
        for (int off = tid * 16; off < CHUNK_B; off += 128 * 16)
            cp16(&sbuf[pc][off], src + off);
        cp_commit();
    }

    const int rotOff  = ((h * 2) * 32 + lane) * 16;       // r=0 entry; r=1 at +512
    const int leftOff = LEFT_OFF + (h * 32 + lane) * 8;

    int rb = 0, ib = 2;
    #pragma unroll 1
    for (int c = 0; c < NCHUNK; ++c) {
        cp_wait1();
        __syncthreads();

        if (c + 2 < NCHUNK) {
            const char* src = g_tab + (size_t)(c + 2) * CHUNK_B;
            for (int off = tid * 16; off < CHUNK_B; off += 128 * 16)
                cp16(&sbuf[ib][off], src + off);
        }
        cp_commit();

        const char* cb = sbuf[rb];
        #pragma unroll
        for (int sl = 0; sl < 3; ++sl) {
            const int t0  = c * CHUNK_L + 2 * sl;
            const bool win = (t0 >= 254 && t0 <= 764);     // seam gate (255,256) active
            const bool act = (h == 0) || win;              // half-1 triangle skip
            const int par = ((c * 3 + sl) & 1);

            if (act) {
                const char* le = cb + (2 * sl) * LAYER_B;
                const char* lo = le + LAYER_B;
                double2 E0 = *reinterpret_cast<const double2*>(le + rotOff);
                double2 E1 = *reinterpret_cast<const double2*>(le + rotOff + 512);
                double2 O0 = *reinterpret_cast<const double2*>(lo + rotOff);
                double2 O1 = *reinterpret_cast<const double2*>(lo + rotOff + 512);
                float2  LF = *reinterpret_cast<const float2*>(lo + leftOff);

                // ---- even layer ----
                rotp(P[0], P[1], E0);
                rotp(P[2], P[3], E1);

                // ---- seam exchange (post-even values) ----
                if (win) {
                    if (h == 0) { if (lane == 31) seam[rp][par][0] = hi_f(P[3]); } // v255
                    else        { if (lane == 0)  seam[rp][par][1] = lo_f(P[0]); } // v256
                    bar_pair(rp + 1);
                }

                // ---- odd layer ----
                float vnext = __shfl_down_sync(0xffffffffu, lo_f(P[0]), 1);   // next lane v0
                if (lane == 31) vnext = (h == 0) ? seam[rp][par][1] : 0.0f;
                float lv = __shfl_up_sync(0xffffffffu, hi_f(P[3]), 1);        // left v7
                if (h == 1 && lane == 0) lv = seam[rp][par][0];

                rotp(P[1], P[2], O0);
                ull Q = pk(hi_f(P[0]), vnext);        // (v4, v8_next)
                rotp(P[3], Q, O1);                     // gates (v3,v4), (v7,v8_next)
                float nv0 = fmaf(LF.x, lo_f(P[0]), -(LF.y * lv));  // left gate, redundant
                P[0] = pk(nv0, lo_f(Q));               // (new v0, new v4)
            }
        }

        rb = (rb == 2) ? 0 : rb + 1;
        ib = (ib == 2) ? 0 : ib + 1;
    }

    // store + bias: wires w+8L+{0..3} = lo halves, w+8L+{4..7} = hi halves
    {
        const float4* bb   = reinterpret_cast<const float4*>(bias + w) + lane * 2;
        float4*       outr = reinterpret_cast<float4*>(out + (size_t)row * N_WIRES + w) + lane * 2;
        float4 b0 = bb[0], b1 = bb[1];
        float4 o0, o1;
        o0.x = lo_f(P[0]) + b0.x; o0.y = lo_f(P[1]) + b0.y;
        o0.z = lo_f(P[2]) + b0.z; o0.w = lo_f(P[3]) + b0.w;
        o1.x = hi_f(P[0]) + b1.x; o1.y = hi_f(P[1]) + b1.y;
        o1.z = hi_f(P[2]) + b1.z; o1.w = hi_f(P[3]) + b1.w;
        outr[0] = o0; outr[1] = o1;
    }
}

extern "C" void kernel_launch(void* const* d_in, const int* in_sizes, int n_in,
                              void* d_out, int out_size) {
    const float* x      = (const float*)d_in[0];
    const float* thetas = (const float*)d_in[1];
    const float* bias   = (const float*)d_in[2];
    float* out = (float*)d_out;

    build_cs_kernel<<<T_PAD, 128>>>(thetas);

    int B = in_sizes[0] / N_WIRES;   // 256
    apply_kernel<<<B / 2, 128>>>(x, bias, out);
}